// round 3
// baseline (speedup 1.0000x reference)
#include <cuda_runtime.h>
#include <math.h>

// Problem constants
#define BB 4
#define SS 4096
#define HH 1024
#define MTOT (BB*SS)          // 16384

#define NEG_INF __int_as_float(0xff800000)

// Scratch (device globals: allocation-free rule)
__device__ float g_q[(size_t)MTOT * HH];
__device__ float g_k[(size_t)MTOT * HH];
__device__ float g_v[(size_t)MTOT * HH];
__device__ float g_p[(size_t)BB * SS * SS];   // scores / probs (lower-tri band used)

// ---------------------------------------------------------------------------
// Kernel 1: QKV projection. C[m,n] = sum_k X[m,k] * W[n,k]  (NT gemm)
// M=16384, N=1024, K=1024. blockIdx.z selects (Wq,g_q),(Wk,g_k),(Wv,g_v).
// 128x128 tile, BK=8, 256 threads, 8x8 micro-tile.
// ---------------------------------------------------------------------------
__global__ __launch_bounds__(256)
void qkv_gemm(const float* __restrict__ X,
              const float* __restrict__ Wq,
              const float* __restrict__ Wk,
              const float* __restrict__ Wv)
{
    const float* W = (blockIdx.z == 0) ? Wq : (blockIdx.z == 1) ? Wk : Wv;
    float* C = (blockIdx.z == 0) ? g_q : (blockIdx.z == 1) ? g_k : g_v;
    const int K = HH, N = HH;

    __shared__ float As[8][128];
    __shared__ float Bs[8][128];

    const int tid  = threadIdx.x;
    const int mBase = blockIdx.y * 128;
    const int nBase = blockIdx.x * 128;

    const int ldRow = tid >> 1;            // 0..127
    const int ldCol = (tid & 1) * 4;       // 0 or 4
    const int ty = tid >> 4;               // 0..15
    const int tx = tid & 15;               // 0..15

    const float* Aptr = X + (size_t)(mBase + ldRow) * K + ldCol;
    const float* Bptr = W + (size_t)(nBase + ldRow) * K + ldCol;

    float acc[8][8];
    #pragma unroll
    for (int i = 0; i < 8; i++)
        #pragma unroll
        for (int j = 0; j < 8; j++) acc[i][j] = 0.f;

    for (int k0 = 0; k0 < K; k0 += 8) {
        float4 av = __ldg((const float4*)(Aptr + k0));
        float4 bv = __ldg((const float4*)(Bptr + k0));
        As[ldCol + 0][ldRow] = av.x;
        As[ldCol + 1][ldRow] = av.y;
        As[ldCol + 2][ldRow] = av.z;
        As[ldCol + 3][ldRow] = av.w;
        Bs[ldCol + 0][ldRow] = bv.x;
        Bs[ldCol + 1][ldRow] = bv.y;
        Bs[ldCol + 2][ldRow] = bv.z;
        Bs[ldCol + 3][ldRow] = bv.w;
        __syncthreads();
        #pragma unroll
        for (int kk = 0; kk < 8; kk++) {
            float a[8], b[8];
            *(float4*)(a)     = *(const float4*)&As[kk][ty * 8];
            *(float4*)(a + 4) = *(const float4*)&As[kk][ty * 8 + 4];
            *(float4*)(b)     = *(const float4*)&Bs[kk][tx * 8];
            *(float4*)(b + 4) = *(const float4*)&Bs[kk][tx * 8 + 4];
            #pragma unroll
            for (int i = 0; i < 8; i++)
                #pragma unroll
                for (int j = 0; j < 8; j++)
                    acc[i][j] += a[i] * b[j];
        }
        __syncthreads();
    }

    #pragma unroll
    for (int i = 0; i < 8; i++) {
        float* cp = C + (size_t)(mBase + ty * 8 + i) * N + nBase + tx * 8;
        *(float4*)(cp)     = make_float4(acc[i][0], acc[i][1], acc[i][2], acc[i][3]);
        *(float4*)(cp + 4) = make_float4(acc[i][4], acc[i][5], acc[i][6], acc[i][7]);
    }
}

// ---------------------------------------------------------------------------
// Kernel 2: scores[b][i][j] = (q[b][i]·k[b][j]) / 32, causal.
// Per-batch NT gemm, M=N=4096, K=1024. Fully-masked tiles are never read
// downstream (softmax + av_gemm are band-limited) -> skip them entirely.
// Diagonal tiles mask elementwise with -inf (softmax exps them to 0).
// ---------------------------------------------------------------------------
__global__ __launch_bounds__(256)
void scores_gemm()
{
    const int b = blockIdx.z;
    const int K = HH;
    const int mBase = blockIdx.y * 128;
    const int nBase = blockIdx.x * 128;

    if (nBase > mBase + 127) return;   // dead tile: nothing downstream reads it

    const int tid = threadIdx.x;
    const int ty = tid >> 4;
    const int tx = tid & 15;

    float* P = g_p + (size_t)b * SS * SS;
    const float* Q = g_q + (size_t)b * SS * HH;
    const float* Kb = g_k + (size_t)b * SS * HH;

    __shared__ float As[8][128];
    __shared__ float Bs[8][128];

    const int ldRow = tid >> 1;
    const int ldCol = (tid & 1) * 4;
    const float* Aptr = Q  + (size_t)(mBase + ldRow) * K + ldCol;
    const float* Bptr = Kb + (size_t)(nBase + ldRow) * K + ldCol;

    float acc[8][8];
    #pragma unroll
    for (int i = 0; i < 8; i++)
        #pragma unroll
        for (int j = 0; j < 8; j++) acc[i][j] = 0.f;

    for (int k0 = 0; k0 < K; k0 += 8) {
        float4 av = __ldg((const float4*)(Aptr + k0));
        float4 bv = __ldg((const float4*)(Bptr + k0));
        As[ldCol + 0][ldRow] = av.x;
        As[ldCol + 1][ldRow] = av.y;
        As[ldCol + 2][ldRow] = av.z;
        As[ldCol + 3][ldRow] = av.w;
        Bs[ldCol + 0][ldRow] = bv.x;
        Bs[ldCol + 1][ldRow] = bv.y;
        Bs[ldCol + 2][ldRow] = bv.z;
        Bs[ldCol + 3][ldRow] = bv.w;
        __syncthreads();
        #pragma unroll
        for (int kk = 0; kk < 8; kk++) {
            float a[8], bfr[8];
            *(float4*)(a)       = *(const float4*)&As[kk][ty * 8];
            *(float4*)(a + 4)   = *(const float4*)&As[kk][ty * 8 + 4];
            *(float4*)(bfr)     = *(const float4*)&Bs[kk][tx * 8];
            *(float4*)(bfr + 4) = *(const float4*)&Bs[kk][tx * 8 + 4];
            #pragma unroll
            for (int i = 0; i < 8; i++)
                #pragma unroll
                for (int j = 0; j < 8; j++)
                    acc[i][j] += a[i] * bfr[j];
        }
        __syncthreads();
    }

    const float scale = 0.03125f;  // 1/sqrt(1024)
    #pragma unroll
    for (int i = 0; i < 8; i++) {
        int row = mBase + ty * 8 + i;
        float* cp = P + (size_t)row * SS + nBase + tx * 8;
        float out[8];
        #pragma unroll
        for (int j = 0; j < 8; j++) {
            int col = nBase + tx * 8 + j;
            out[j] = (col <= row) ? acc[i][j] * scale : NEG_INF;
        }
        *(float4*)(cp)     = make_float4(out[0], out[1], out[2], out[3]);
        *(float4*)(cp + 4) = make_float4(out[4], out[5], out[6], out[7]);
    }
}

// ---------------------------------------------------------------------------
// Kernel 3: row softmax in-place on g_p, band-limited: row i only touches
// j < bound = (i/128+1)*128 (exactly what av_gemm consumes). In-tile masked
// entries are -inf -> exp to 0.
// ---------------------------------------------------------------------------
__global__ __launch_bounds__(256)
void softmax_rows()
{
    const int r = blockIdx.x;                 // 0..16383
    const int i = r & (SS - 1);               // row within batch
    const int bound = ((i >> 7) + 1) << 7;    // tile-rounded causal bound
    float* row = g_p + (size_t)r * SS;

    __shared__ float buf[SS];                 // 16 KB (worst case)
    __shared__ float red[8];

    const int tid = threadIdx.x;
    const int lane = tid & 31;
    const int wid = tid >> 5;

    float mx = NEG_INF;
    for (int j = tid; j < bound; j += 256) {
        float v = row[j];
        buf[j] = v;
        mx = fmaxf(mx, v);
    }
    #pragma unroll
    for (int o = 16; o > 0; o >>= 1)
        mx = fmaxf(mx, __shfl_xor_sync(0xffffffffu, mx, o));
    if (lane == 0) red[wid] = mx;
    __syncthreads();
    if (wid == 0) {
        float m = red[lane & 7];
        #pragma unroll
        for (int o = 4; o > 0; o >>= 1)
            m = fmaxf(m, __shfl_xor_sync(0xffffffffu, m, o));
        if (lane == 0) red[0] = m;
    }
    __syncthreads();
    mx = red[0];

    float sum = 0.f;
    for (int j = tid; j < bound; j += 256) {
        float e = __expf(buf[j] - mx);
        buf[j] = e;
        sum += e;
    }
    #pragma unroll
    for (int o = 16; o > 0; o >>= 1)
        sum += __shfl_xor_sync(0xffffffffu, sum, o);
    __syncthreads();
    if (lane == 0) red[wid] = sum;
    __syncthreads();
    if (wid == 0) {
        float s = red[lane & 7];
        #pragma unroll
        for (int o = 4; o > 0; o >>= 1)
            s += __shfl_xor_sync(0xffffffffu, s, o);
        if (lane == 0) red[0] = s;
    }
    __syncthreads();
    const float inv = 1.0f / red[0];

    for (int j = tid; j < bound; j += 256)
        row[j] = buf[j] * inv;
}

// ---------------------------------------------------------------------------
// Kernel 4: out[b] = P[b] @ v[b]. NN gemm per batch, M=4096, N=1024, K=4096,
// K-loop bounded by causal structure: k < (mTile+1)*128.
// ---------------------------------------------------------------------------
__global__ __launch_bounds__(256)
void av_gemm(float* __restrict__ out)
{
    const int b = blockIdx.z;
    const int mBase = blockIdx.y * 128;
    const int nBase = blockIdx.x * 128;
    const int tid = threadIdx.x;
    const int ty = tid >> 4;
    const int tx = tid & 15;

    const float* P = g_p + (size_t)b * SS * SS;
    const float* V = g_v + (size_t)b * SS * HH;
    float* C = out + (size_t)b * SS * HH;

    __shared__ float As[8][128];
    __shared__ float Bs[8][128];

    // A (P) loader: 128 rows x 8 k, transposed into As
    const int aRow = tid >> 1;
    const int aCol = (tid & 1) * 4;
    const float* Aptr = P + (size_t)(mBase + aRow) * SS + aCol;
    // B (V) loader: 8 k-rows x 128 n, direct
    const int bRow = tid >> 5;          // 0..7
    const int bCol = (tid & 31) * 4;    // 0..124
    const float* Bptr = V + (size_t)bRow * HH + nBase + bCol;

    float acc[8][8];
    #pragma unroll
    for (int i = 0; i < 8; i++)
        #pragma unroll
        for (int j = 0; j < 8; j++) acc[i][j] = 0.f;

    const int Klim = (blockIdx.y + 1) * 128;   // causal bound

    for (int k0 = 0; k0 < Klim; k0 += 8) {
        float4 av = __ldg((const float4*)(Aptr + k0));
        float4 bv = __ldg((const float4*)(Bptr + (size_t)k0 * HH));
        As[aCol + 0][aRow] = av.x;
        As[aCol + 1][aRow] = av.y;
        As[aCol + 2][aRow] = av.z;
        As[aCol + 3][aRow] = av.w;
        *(float4*)&Bs[bRow][bCol] = bv;
        __syncthreads();
        #pragma unroll
        for (int kk = 0; kk < 8; kk++) {
            float a[8], bfr[8];
            *(float4*)(a)       = *(const float4*)&As[kk][ty * 8];
            *(float4*)(a + 4)   = *(const float4*)&As[kk][ty * 8 + 4];
            *(float4*)(bfr)     = *(const float4*)&Bs[kk][tx * 8];
            *(float4*)(bfr + 4) = *(const float4*)&Bs[kk][tx * 8 + 4];
            #pragma unroll
            for (int i = 0; i < 8; i++)
                #pragma unroll
                for (int j = 0; j < 8; j++)
                    acc[i][j] += a[i] * bfr[j];
        }
        __syncthreads();
    }

    #pragma unroll
    for (int i = 0; i < 8; i++) {
        float* cp = C + (size_t)(mBase + ty * 8 + i) * HH + nBase + tx * 8;
        *(float4*)(cp)     = make_float4(acc[i][0], acc[i][1], acc[i][2], acc[i][3]);
        *(float4*)(cp + 4) = make_float4(acc[i][4], acc[i][5], acc[i][6], acc[i][7]);
    }
}

// ---------------------------------------------------------------------------
extern "C" void kernel_launch(void* const* d_in, const int* in_sizes, int n_in,
                              void* d_out, int out_size)
{
    const float* x  = (const float*)d_in[0];
    const float* Wq = (const float*)d_in[1];
    const float* Wk = (const float*)d_in[2];
    const float* Wv = (const float*)d_in[3];
    float* out = (float*)d_out;

    (void)in_sizes; (void)n_in; (void)out_size;

    // 1) QKV projections
    qkv_gemm<<<dim3(HH / 128, MTOT / 128, 3), 256>>>(x, Wq, Wk, Wv);
    // 2) causal scaled scores (band only)
    scores_gemm<<<dim3(SS / 128, SS / 128, BB), 256>>>();
    // 3) band-limited row softmax
    softmax_rows<<<BB * SS, 256>>>();
    // 4) P @ V (causally K-bounded)
    av_gemm<<<dim3(HH / 128, SS / 128, BB), 256>>>(out);
}

// round 4
// speedup vs baseline: 1.2455x; 1.2455x over previous
#include <cuda_runtime.h>
#include <cuda_bf16.h>
#include <mma.h>
#include <math.h>

using namespace nvcuda;

// Problem constants
#define BB 4
#define SS 4096
#define HH 1024
#define MTOT (BB*SS)          // 16384

#define NEG_INF __int_as_float(0xff800000)

// Scratch (device globals: allocation-free rule)
__device__ float g_q[(size_t)MTOT * HH];
__device__ float g_k[(size_t)MTOT * HH];
__device__ float g_v[(size_t)MTOT * HH];
__device__ float g_p[(size_t)BB * SS * SS];   // scores / probs (lower-tri band used)

// fp32 -> bf16 hi/lo split (error ~2^-18 after 3-term recombination)
__device__ __forceinline__ void cvt_split(float v, __nv_bfloat16* hi, __nv_bfloat16* lo)
{
    __nv_bfloat16 h = __float2bfloat16(v);
    *hi = h;
    *lo = __float2bfloat16(v - __bfloat162float(h));
}

// ---------------------------------------------------------------------------
// Kernel 1: QKV projection. C[m,n] = sum_k X[m,k] * W[n,k]  (NT)
// Tensor-core: 128x128 tile, BK=32, 8 warps (2x4), warp tile 64x32,
// wmma 16x16x16 bf16, split-accumulate ah*bh + ah*bl + al*bh in fp32.
// ---------------------------------------------------------------------------
__global__ __launch_bounds__(256)
void qkv_gemm(const float* __restrict__ X,
              const float* __restrict__ Wq,
              const float* __restrict__ Wk,
              const float* __restrict__ Wv)
{
    const float* W = (blockIdx.z == 0) ? Wq : (blockIdx.z == 1) ? Wk : Wv;
    float* C = (blockIdx.z == 0) ? g_q : (blockIdx.z == 1) ? g_k : g_v;

    __shared__ __nv_bfloat16 Ah[128][40], Al[128][40];
    __shared__ __nv_bfloat16 Bh[128][40], Bl[128][40];

    const int tid = threadIdx.x;
    const int wid = tid >> 5;
    const int wm = wid & 1;        // 0..1 -> 64-row half
    const int wn = wid >> 1;       // 0..3 -> 32-col quarter
    const int mBase = blockIdx.y * 128;
    const int nBase = blockIdx.x * 128;

    wmma::fragment<wmma::accumulator, 16, 16, 16, float> acc[4][2];
    #pragma unroll
    for (int i = 0; i < 4; i++)
        #pragma unroll
        for (int j = 0; j < 2; j++)
            wmma::fill_fragment(acc[i][j], 0.0f);

    const int lrow = tid >> 1;           // 0..127
    const int lcb  = (tid & 1) * 16;     // 0 or 16
    const float* Ap = X + (size_t)(mBase + lrow) * HH + lcb;
    const float* Bp = W + (size_t)(nBase + lrow) * HH + lcb;

    for (int k0 = 0; k0 < HH; k0 += 32) {
        #pragma unroll
        for (int q = 0; q < 4; q++) {
            float4 a = __ldg((const float4*)(Ap + k0 + q * 4));
            float4 b = __ldg((const float4*)(Bp + k0 + q * 4));
            int c = lcb + q * 4;
            cvt_split(a.x, &Ah[lrow][c+0], &Al[lrow][c+0]);
            cvt_split(a.y, &Ah[lrow][c+1], &Al[lrow][c+1]);
            cvt_split(a.z, &Ah[lrow][c+2], &Al[lrow][c+2]);
            cvt_split(a.w, &Ah[lrow][c+3], &Al[lrow][c+3]);
            cvt_split(b.x, &Bh[lrow][c+0], &Bl[lrow][c+0]);
            cvt_split(b.y, &Bh[lrow][c+1], &Bl[lrow][c+1]);
            cvt_split(b.z, &Bh[lrow][c+2], &Bl[lrow][c+2]);
            cvt_split(b.w, &Bh[lrow][c+3], &Bl[lrow][c+3]);
        }
        __syncthreads();

        #pragma unroll
        for (int kk = 0; kk < 32; kk += 16) {
            wmma::fragment<wmma::matrix_a, 16, 16, 16, __nv_bfloat16, wmma::row_major> ah[4], al[4];
            wmma::fragment<wmma::matrix_b, 16, 16, 16, __nv_bfloat16, wmma::col_major> bh[2], bl[2];
            #pragma unroll
            for (int i = 0; i < 4; i++) {
                wmma::load_matrix_sync(ah[i], &Ah[wm * 64 + i * 16][kk], 40);
                wmma::load_matrix_sync(al[i], &Al[wm * 64 + i * 16][kk], 40);
            }
            #pragma unroll
            for (int j = 0; j < 2; j++) {
                wmma::load_matrix_sync(bh[j], &Bh[wn * 32 + j * 16][kk], 40);
                wmma::load_matrix_sync(bl[j], &Bl[wn * 32 + j * 16][kk], 40);
            }
            #pragma unroll
            for (int i = 0; i < 4; i++)
                #pragma unroll
                for (int j = 0; j < 2; j++) {
                    wmma::mma_sync(acc[i][j], ah[i], bh[j], acc[i][j]);
                    wmma::mma_sync(acc[i][j], ah[i], bl[j], acc[i][j]);
                    wmma::mma_sync(acc[i][j], al[i], bh[j], acc[i][j]);
                }
        }
        __syncthreads();
    }

    #pragma unroll
    for (int i = 0; i < 4; i++)
        #pragma unroll
        for (int j = 0; j < 2; j++) {
            float* cp = C + (size_t)(mBase + wm * 64 + i * 16) * HH + nBase + wn * 32 + j * 16;
            wmma::store_matrix_sync(cp, acc[i][j], HH, wmma::mem_row_major);
        }
}

// ---------------------------------------------------------------------------
// Kernel 2: causal scaled scores, tensor-core NT, masked epilogue via smem.
// Dead tiles (nBase > mBase+127) skipped; downstream is band-limited.
// ---------------------------------------------------------------------------
__global__ __launch_bounds__(256)
void scores_gemm()
{
    const int mBase = blockIdx.y * 128;
    const int nBase = blockIdx.x * 128;
    if (nBase > mBase + 127) return;

    const int b = blockIdx.z;
    float* P = g_p + (size_t)b * SS * SS;
    const float* Q  = g_q + (size_t)b * SS * HH;
    const float* Kb = g_k + (size_t)b * SS * HH;

    __shared__ __nv_bfloat16 Ah[128][40], Al[128][40];
    __shared__ __nv_bfloat16 Bh[128][40], Bl[128][40];

    const int tid = threadIdx.x;
    const int wid = tid >> 5;
    const int lane = tid & 31;
    const int wm = wid & 1;
    const int wn = wid >> 1;

    wmma::fragment<wmma::accumulator, 16, 16, 16, float> acc[4][2];
    #pragma unroll
    for (int i = 0; i < 4; i++)
        #pragma unroll
        for (int j = 0; j < 2; j++)
            wmma::fill_fragment(acc[i][j], 0.0f);

    const int lrow = tid >> 1;
    const int lcb  = (tid & 1) * 16;
    const float* Ap = Q  + (size_t)(mBase + lrow) * HH + lcb;
    const float* Bp = Kb + (size_t)(nBase + lrow) * HH + lcb;

    for (int k0 = 0; k0 < HH; k0 += 32) {
        #pragma unroll
        for (int q = 0; q < 4; q++) {
            float4 a = __ldg((const float4*)(Ap + k0 + q * 4));
            float4 bv = __ldg((const float4*)(Bp + k0 + q * 4));
            int c = lcb + q * 4;
            cvt_split(a.x,  &Ah[lrow][c+0], &Al[lrow][c+0]);
            cvt_split(a.y,  &Ah[lrow][c+1], &Al[lrow][c+1]);
            cvt_split(a.z,  &Ah[lrow][c+2], &Al[lrow][c+2]);
            cvt_split(a.w,  &Ah[lrow][c+3], &Al[lrow][c+3]);
            cvt_split(bv.x, &Bh[lrow][c+0], &Bl[lrow][c+0]);
            cvt_split(bv.y, &Bh[lrow][c+1], &Bl[lrow][c+1]);
            cvt_split(bv.z, &Bh[lrow][c+2], &Bl[lrow][c+2]);
            cvt_split(bv.w, &Bh[lrow][c+3], &Bl[lrow][c+3]);
        }
        __syncthreads();

        #pragma unroll
        for (int kk = 0; kk < 32; kk += 16) {
            wmma::fragment<wmma::matrix_a, 16, 16, 16, __nv_bfloat16, wmma::row_major> ah[4], al[4];
            wmma::fragment<wmma::matrix_b, 16, 16, 16, __nv_bfloat16, wmma::col_major> bh[2], bl[2];
            #pragma unroll
            for (int i = 0; i < 4; i++) {
                wmma::load_matrix_sync(ah[i], &Ah[wm * 64 + i * 16][kk], 40);
                wmma::load_matrix_sync(al[i], &Al[wm * 64 + i * 16][kk], 40);
            }
            #pragma unroll
            for (int j = 0; j < 2; j++) {
                wmma::load_matrix_sync(bh[j], &Bh[wn * 32 + j * 16][kk], 40);
                wmma::load_matrix_sync(bl[j], &Bl[wn * 32 + j * 16][kk], 40);
            }
            #pragma unroll
            for (int i = 0; i < 4; i++)
                #pragma unroll
                for (int j = 0; j < 2; j++) {
                    wmma::mma_sync(acc[i][j], ah[i], bh[j], acc[i][j]);
                    wmma::mma_sync(acc[i][j], ah[i], bl[j], acc[i][j]);
                    wmma::mma_sync(acc[i][j], al[i], bh[j], acc[i][j]);
                }
        }
        __syncthreads();
    }

    // Masked epilogue: frag -> per-warp smem scratch -> masked global write.
    // Reuse Ah (10240B >= 8 warps * 16*16*4 = 8192B); safe after the last sync.
    float* scratch = (float*)&Ah[0][0];
    float* ws = scratch + wid * 16 * 16;
    const float scale = 0.03125f;  // 1/sqrt(1024)
    const int r   = lane >> 1;
    const int cb2 = (lane & 1) * 8;

    #pragma unroll
    for (int i = 0; i < 4; i++)
        #pragma unroll
        for (int j = 0; j < 2; j++) {
            wmma::store_matrix_sync(ws, acc[i][j], 16, wmma::mem_row_major);
            __syncwarp();
            int gr  = mBase + wm * 64 + i * 16 + r;
            int gc0 = nBase + wn * 32 + j * 16 + cb2;
            float o[8];
            #pragma unroll
            for (int c = 0; c < 8; c++) {
                float v = ws[r * 16 + cb2 + c];
                o[c] = (gc0 + c <= gr) ? v * scale : NEG_INF;
            }
            float* cp = P + (size_t)gr * SS + gc0;
            *(float4*)(cp)     = make_float4(o[0], o[1], o[2], o[3]);
            *(float4*)(cp + 4) = make_float4(o[4], o[5], o[6], o[7]);
            __syncwarp();
        }
}

// ---------------------------------------------------------------------------
// Kernel 3: band-limited row softmax in-place on g_p.
// ---------------------------------------------------------------------------
__global__ __launch_bounds__(256)
void softmax_rows()
{
    const int r = blockIdx.x;                 // 0..16383
    const int i = r & (SS - 1);
    const int bound = ((i >> 7) + 1) << 7;    // tile-rounded causal bound
    float* row = g_p + (size_t)r * SS;

    __shared__ float buf[SS];
    __shared__ float red[8];

    const int tid = threadIdx.x;
    const int lane = tid & 31;
    const int wid = tid >> 5;

    float mx = NEG_INF;
    for (int j = tid; j < bound; j += 256) {
        float v = row[j];
        buf[j] = v;
        mx = fmaxf(mx, v);
    }
    #pragma unroll
    for (int o = 16; o > 0; o >>= 1)
        mx = fmaxf(mx, __shfl_xor_sync(0xffffffffu, mx, o));
    if (lane == 0) red[wid] = mx;
    __syncthreads();
    if (wid == 0) {
        float m = red[lane & 7];
        #pragma unroll
        for (int o = 4; o > 0; o >>= 1)
            m = fmaxf(m, __shfl_xor_sync(0xffffffffu, m, o));
        if (lane == 0) red[0] = m;
    }
    __syncthreads();
    mx = red[0];

    float sum = 0.f;
    for (int j = tid; j < bound; j += 256) {
        float e = __expf(buf[j] - mx);
        buf[j] = e;
        sum += e;
    }
    #pragma unroll
    for (int o = 16; o > 0; o >>= 1)
        sum += __shfl_xor_sync(0xffffffffu, sum, o);
    __syncthreads();
    if (lane == 0) red[wid] = sum;
    __syncthreads();
    if (wid == 0) {
        float s = red[lane & 7];
        #pragma unroll
        for (int o = 4; o > 0; o >>= 1)
            s += __shfl_xor_sync(0xffffffffu, s, o);
        if (lane == 0) red[0] = s;
    }
    __syncthreads();
    const float inv = 1.0f / red[0];

    for (int j = tid; j < bound; j += 256)
        row[j] = buf[j] * inv;
}

// ---------------------------------------------------------------------------
// Kernel 4: out[b] = P[b] @ v[b], tensor-core NN, causally K-bounded.
// A = P (row-major M x K), B = V (row-major K x N -> matrix_b row_major).
// ---------------------------------------------------------------------------
__global__ __launch_bounds__(256)
void av_gemm(float* __restrict__ out)
{
    const int b = blockIdx.z;
    const int mBase = blockIdx.y * 128;
    const int nBase = blockIdx.x * 128;

    const float* P = g_p + (size_t)b * SS * SS;
    const float* V = g_v + (size_t)b * SS * HH;
    float* C = out + (size_t)b * SS * HH;

    __shared__ __nv_bfloat16 Ph[128][40], Pl[128][40];
    __shared__ __nv_bfloat16 Vh[32][136], Vl[32][136];

    const int tid = threadIdx.x;
    const int wid = tid >> 5;
    const int wm = wid & 1;
    const int wn = wid >> 1;

    wmma::fragment<wmma::accumulator, 16, 16, 16, float> acc[4][2];
    #pragma unroll
    for (int i = 0; i < 4; i++)
        #pragma unroll
        for (int j = 0; j < 2; j++)
            wmma::fill_fragment(acc[i][j], 0.0f);

    // P loader: 128 rows x 32 k
    const int lrow = tid >> 1;
    const int lcb  = (tid & 1) * 16;
    const float* Pp = P + (size_t)(mBase + lrow) * SS + lcb;
    // V loader: 32 k-rows x 128 n
    const int vrow = tid >> 3;          // 0..31
    const int vcb  = (tid & 7) * 16;    // 0..112
    const float* Vp = V + (size_t)vrow * HH + nBase + vcb;

    const int Klim = (blockIdx.y + 1) * 128;  // causal bound

    for (int k0 = 0; k0 < Klim; k0 += 32) {
        #pragma unroll
        for (int q = 0; q < 4; q++) {
            float4 a = __ldg((const float4*)(Pp + k0 + q * 4));
            float4 v = __ldg((const float4*)(Vp + (size_t)k0 * HH + q * 4));
            int c  = lcb + q * 4;
            int vc = vcb + q * 4;
            cvt_split(a.x, &Ph[lrow][c+0], &Pl[lrow][c+0]);
            cvt_split(a.y, &Ph[lrow][c+1], &Pl[lrow][c+1]);
            cvt_split(a.z, &Ph[lrow][c+2], &Pl[lrow][c+2]);
            cvt_split(a.w, &Ph[lrow][c+3], &Pl[lrow][c+3]);
            cvt_split(v.x, &Vh[vrow][vc+0], &Vl[vrow][vc+0]);
            cvt_split(v.y, &Vh[vrow][vc+1], &Vl[vrow][vc+1]);
            cvt_split(v.z, &Vh[vrow][vc+2], &Vl[vrow][vc+2]);
            cvt_split(v.w, &Vh[vrow][vc+3], &Vl[vrow][vc+3]);
        }
        __syncthreads();

        #pragma unroll
        for (int kk = 0; kk < 32; kk += 16) {
            wmma::fragment<wmma::matrix_a, 16, 16, 16, __nv_bfloat16, wmma::row_major> ah[4], al[4];
            wmma::fragment<wmma::matrix_b, 16, 16, 16, __nv_bfloat16, wmma::row_major> bh[2], bl[2];
            #pragma unroll
            for (int i = 0; i < 4; i++) {
                wmma::load_matrix_sync(ah[i], &Ph[wm * 64 + i * 16][kk], 40);
                wmma::load_matrix_sync(al[i], &Pl[wm * 64 + i * 16][kk], 40);
            }
            #pragma unroll
            for (int j = 0; j < 2; j++) {
                wmma::load_matrix_sync(bh[j], &Vh[kk][wn * 32 + j * 16], 136);
                wmma::load_matrix_sync(bl[j], &Vl[kk][wn * 32 + j * 16], 136);
            }
            #pragma unroll
            for (int i = 0; i < 4; i++)
                #pragma unroll
                for (int j = 0; j < 2; j++) {
                    wmma::mma_sync(acc[i][j], ah[i], bh[j], acc[i][j]);
                    wmma::mma_sync(acc[i][j], ah[i], bl[j], acc[i][j]);
                    wmma::mma_sync(acc[i][j], al[i], bh[j], acc[i][j]);
                }
        }
        __syncthreads();
    }

    #pragma unroll
    for (int i = 0; i < 4; i++)
        #pragma unroll
        for (int j = 0; j < 2; j++) {
            float* cp = C + (size_t)(mBase + wm * 64 + i * 16) * HH + nBase + wn * 32 + j * 16;
            wmma::store_matrix_sync(cp, acc[i][j], HH, wmma::mem_row_major);
        }
}

// ---------------------------------------------------------------------------
extern "C" void kernel_launch(void* const* d_in, const int* in_sizes, int n_in,
                              void* d_out, int out_size)
{
    const float* x  = (const float*)d_in[0];
    const float* Wq = (const float*)d_in[1];
    const float* Wk = (const float*)d_in[2];
    const float* Wv = (const float*)d_in[3];
    float* out = (float*)d_out;

    (void)in_sizes; (void)n_in; (void)out_size;

    // 1) QKV projections (tensor cores, bf16 split)
    qkv_gemm<<<dim3(HH / 128, MTOT / 128, 3), 256>>>(x, Wq, Wk, Wv);
    // 2) causal scaled scores (band only)
    scores_gemm<<<dim3(SS / 128, SS / 128, BB), 256>>>();
    // 3) band-limited row softmax
    softmax_rows<<<BB * SS, 256>>>();
    // 4) P @ V (causally K-bounded)
    av_gemm<<<dim3(HH / 128, SS / 128, BB), 256>>>(out);
}